// round 1
// baseline (speedup 1.0000x reference)
#include <cuda_runtime.h>

// GeneratorCell: B=128 batches, M=32 queue rows, N=64 strokes, K=2048 stroke length
#define Bn 128
#define Mn 32
#define Nn 64
#define Kn 2048
#define NT 256

__device__ __forceinline__ float sigmoidf_(float x) {
    return 1.0f / (1.0f + __expf(-x));
}

__global__ __launch_bounds__(NT) void gen_cell_kernel(
    const float* __restrict__ qt1,      // [B, M, N, 2]
    const float* __restrict__ ht1,      // [B, N, 2]
    const float* __restrict__ zt,       // [B, N]
    const float* __restrict__ alpha_t,  // [B, N]
    const float* __restrict__ conv_w,   // [2, 2, M+1, 1]
    const float* __restrict__ conv_b,   // [2]
    const float* __restrict__ W_xr, const float* __restrict__ W_hr, const float* __restrict__ b_r,
    const float* __restrict__ W_xu, const float* __restrict__ W_hu, const float* __restrict__ b_u,
    const float* __restrict__ W_xn, const float* __restrict__ W_hn, const float* __restrict__ b_n,
    const float* __restrict__ lin_w,    // [N, 2N]
    const float* __restrict__ lin_b,    // [N]
    const float* __restrict__ W_emb,    // [K, 2]
    float* __restrict__ out)            // st [B,N,2] | qt [B,M,N,2] | ht [B,N,2]
{
    __shared__ float2 s_emb[Kn];      // 16 KB
    __shared__ float  s_coef[Nn];
    __shared__ float  s_ht[2 * Nn];

    const int b   = blockIdx.x;
    const int tid = threadIdx.x;
    const float* q = qt1 + (size_t)b * Mn * Nn * 2;

    // ---- stage W_emb into shared (float2 per k) ----
    const float2* we_g = (const float2*)W_emb;
    #pragma unroll 4
    for (int i = tid; i < Kn; i += NT) s_emb[i] = we_g[i];

    // ---- phase 1: conv + GRU per stroke n (threads 0..63) ----
    if (tid < Nn) {
        const int n = tid;
        float h0 = conv_b[0], h1 = conv_b[1];
        #pragma unroll
        for (int c = 0; c < 2; c++) {
            const float* w0 = conv_w + 0 * 2 * (Mn + 1) + c * (Mn + 1);
            const float* w1 = conv_w + 1 * 2 * (Mn + 1) + c * (Mn + 1);
            #pragma unroll 8
            for (int h = 0; h < Mn; h++) {
                float v = q[(h * Nn + n) * 2 + c];
                h0 = fmaf(v, w0[h], h0);
                h1 = fmaf(v, w1[h], h1);
            }
            float v = ht1[((size_t)b * Nn + n) * 2 + c];
            h0 = fmaf(v, w0[Mn], h0);
            h1 = fmaf(v, w1[Mn], h1);
        }

        const float x0 = zt[b * Nn + n];
        const float x1 = alpha_t[b * Nn + n];

        // gate[o] = x0*Wx[0,o] + x1*Wx[1,o] + h0*Wh[0,o] + h1*Wh[1,o] + bias[o]
        float r0 = sigmoidf_(fmaf(x0, W_xr[0], fmaf(x1, W_xr[2], fmaf(h0, W_hr[0], fmaf(h1, W_hr[2], b_r[0])))));
        float r1 = sigmoidf_(fmaf(x0, W_xr[1], fmaf(x1, W_xr[3], fmaf(h0, W_hr[1], fmaf(h1, W_hr[3], b_r[1])))));
        float u0 = sigmoidf_(fmaf(x0, W_xu[0], fmaf(x1, W_xu[2], fmaf(h0, W_hu[0], fmaf(h1, W_hu[2], b_u[0])))));
        float u1 = sigmoidf_(fmaf(x0, W_xu[1], fmaf(x1, W_xu[3], fmaf(h0, W_hu[1], fmaf(h1, W_hu[3], b_u[1])))));

        const float rh0 = r0 * h0, rh1 = r1 * h1;
        float nt0 = tanhf(fmaf(x0, W_xn[0], fmaf(x1, W_xn[2], fmaf(rh0, W_hn[0], fmaf(rh1, W_hn[2], b_n[0])))));
        float nt1 = tanhf(fmaf(x0, W_xn[1], fmaf(x1, W_xn[3], fmaf(rh0, W_hn[1], fmaf(rh1, W_hn[3], b_n[1])))));

        const float hp0 = ht1[((size_t)b * Nn + n) * 2 + 0];
        const float hp1 = ht1[((size_t)b * Nn + n) * 2 + 1];
        const float hn0 = u0 * hp0 + (1.0f - u0) * nt0;
        const float hn1 = u1 * hp1 + (1.0f - u1) * nt1;

        s_ht[2 * n + 0] = hn0;
        s_ht[2 * n + 1] = hn1;

        // ht output block
        const size_t off_ht = (size_t)Bn * Nn * 2 + (size_t)Bn * Mn * Nn * 2;
        out[off_ht + ((size_t)b * Nn + n) * 2 + 0] = hn0;
        out[off_ht + ((size_t)b * Nn + n) * 2 + 1] = hn1;
    }
    __syncthreads();

    // ---- phase 2: it[n] = dot(ht_flat, lin_w[n,:]) + lin_b[n]; coef = it*alpha ----
    if (tid < Nn) {
        const int n = tid;
        float acc = lin_b[n];
        const float* lw = lin_w + (size_t)n * 2 * Nn;
        #pragma unroll 8
        for (int j = 0; j < 2 * Nn; j++) acc = fmaf(s_ht[j], lw[j], acc);
        s_coef[n] = acc * alpha_t[b * Nn + n];
    }
    __syncthreads();

    // ---- phase 3: overlap-add convolution + output assembly ----
    // f[p,:] = sum_{n in window} coef[n] * W_emb[p-n,:]
    // p in [0, N + M*N): covers st (p<N) and full qt (j = p-N in [0, M*N))
    const int P = Nn + Mn * Nn;  // 2112
    for (int p = tid; p < P; p += NT) {
        float fx = 0.0f, fy = 0.0f;
        const int n0 = max(0, p - (Kn - 1));
        const int n1 = min(Nn - 1, p);
        #pragma unroll 8
        for (int n = n0; n <= n1; n++) {
            const float c = s_coef[n];      // warp-uniform -> broadcast
            const float2 w = s_emb[p - n];  // consecutive lanes -> conflict-free
            fx = fmaf(c, w.x, fx);
            fy = fmaf(c, w.y, fy);
        }
        if (p < Nn) {
            // st[b,p,:] = qt1[b,0,p,:] + f[p,:]
            out[((size_t)b * Nn + p) * 2 + 0] = q[p * 2 + 0] + fx;
            out[((size_t)b * Nn + p) * 2 + 1] = q[p * 2 + 1] + fy;
        } else {
            const int j = p - Nn;  // [0, M*N)
            float qs0 = 0.0f, qs1 = 0.0f;
            if (j < (Mn - 1) * Nn) {  // shifted queue row
                qs0 = q[(j + Nn) * 2 + 0];
                qs1 = q[(j + Nn) * 2 + 1];
            }
            const size_t off_qt = (size_t)Bn * Nn * 2 + ((size_t)b * Mn * Nn + j) * 2;
            out[off_qt + 0] = qs0 + fx;
            out[off_qt + 1] = qs1 + fy;
        }
    }
}

extern "C" void kernel_launch(void* const* d_in, const int* in_sizes, int n_in,
                              void* d_out, int out_size) {
    const float* qt1     = (const float*)d_in[0];
    const float* ht1     = (const float*)d_in[1];
    const float* zt      = (const float*)d_in[2];
    const float* alpha_t = (const float*)d_in[3];
    const float* conv_w  = (const float*)d_in[4];
    const float* conv_b  = (const float*)d_in[5];
    const float* W_xr    = (const float*)d_in[6];
    const float* W_hr    = (const float*)d_in[7];
    const float* b_r     = (const float*)d_in[8];
    const float* W_xu    = (const float*)d_in[9];
    const float* W_hu    = (const float*)d_in[10];
    const float* b_u     = (const float*)d_in[11];
    const float* W_xn    = (const float*)d_in[12];
    const float* W_hn    = (const float*)d_in[13];
    const float* b_n     = (const float*)d_in[14];
    const float* lin_w   = (const float*)d_in[15];
    const float* lin_b   = (const float*)d_in[16];
    const float* W_emb   = (const float*)d_in[17];

    gen_cell_kernel<<<Bn, NT>>>(qt1, ht1, zt, alpha_t, conv_w, conv_b,
                                W_xr, W_hr, b_r, W_xu, W_hu, b_u,
                                W_xn, W_hn, b_n, lin_w, lin_b, W_emb,
                                (float*)d_out);
}

// round 2
// speedup vs baseline: 1.5551x; 1.5551x over previous
#include <cuda_runtime.h>

// GeneratorCell: B=128, M=32 queue rows, N=64 strokes, K=2048 stroke length
#define Bn 128
#define Mn 32
#define Nn 64
#define Kn 2048
#define NT 192
#define Cn 11                      // consecutive p's per thread; 192*11 = 2112 = N + M*N
#define PAD 64
#define EMB_SZ (PAD + Kn + PAD)    // zero-padded emb => branch-free inner loop

typedef unsigned long long ull;

__device__ __forceinline__ float sigmoidf_(float x) { return 1.0f / (1.0f + __expf(-x)); }

__device__ __forceinline__ ull pack2(float x, float y) {
    ull r; asm("mov.b64 %0, {%1,%2};" : "=l"(r) : "f"(x), "f"(y)); return r;
}
__device__ __forceinline__ void unpack2(ull v, float& x, float& y) {
    asm("mov.b64 {%0,%1}, %2;" : "=f"(x), "=f"(y) : "l"(v));
}
// packed f32x2 FMA (sm_100+): d = a*b + c per 32-bit lane
__device__ __forceinline__ ull ffma2(ull a, ull b, ull c) {
    ull d; asm("fma.rn.f32x2 %0, %1, %2, %3;" : "=l"(d) : "l"(a), "l"(b), "l"(c)); return d;
}

__global__ __launch_bounds__(NT) void gen_cell_kernel(
    const float* __restrict__ qt1,      // [B, M, N, 2]
    const float* __restrict__ ht1,      // [B, N, 2]
    const float* __restrict__ zt,       // [B, N]
    const float* __restrict__ alpha_t,  // [B, N]
    const float* __restrict__ conv_w,   // [2, 2, M+1, 1]
    const float* __restrict__ conv_b,   // [2]
    const float* __restrict__ W_xr, const float* __restrict__ W_hr, const float* __restrict__ b_r,
    const float* __restrict__ W_xu, const float* __restrict__ W_hu, const float* __restrict__ b_u,
    const float* __restrict__ W_xn, const float* __restrict__ W_hn, const float* __restrict__ b_n,
    const float* __restrict__ lin_w,    // [N, 2N]
    const float* __restrict__ lin_b,    // [N]
    const float* __restrict__ W_emb,    // [K, 2]
    float* __restrict__ out)            // st [B,N,2] | qt [B,M,N,2] | ht [B,N,2]
{
    __shared__ float s_ex[EMB_SZ];      // emb channel x, zero-padded
    __shared__ float s_ey[EMB_SZ];      // emb channel y, zero-padded
    __shared__ ull   s_coef2[Nn];       // (coef, coef) packed f32x2
    __shared__ float s_ht[2 * Nn];

    const int b   = blockIdx.x;
    const int tid = threadIdx.x;
    const float*  q  = qt1 + (size_t)b * Mn * Nn * 2;
    const float2* qf = (const float2*)q;

    if (tid >= 64) {
        // ---- staging crew (128 threads): W_emb -> SoA shared + zero pads ----
        const int t2 = tid - 64;
        if (t2 < PAD) {
            s_ex[t2] = 0.0f; s_ey[t2] = 0.0f;
            s_ex[PAD + Kn + t2] = 0.0f; s_ey[PAD + Kn + t2] = 0.0f;
        }
        const float4* we4 = (const float4*)W_emb;   // 2 emb entries per float4
        #pragma unroll
        for (int i = t2; i < Kn / 2; i += 128) {
            float4 w = we4[i];
            s_ex[PAD + 2 * i]     = w.x; s_ey[PAD + 2 * i]     = w.y;
            s_ex[PAD + 2 * i + 1] = w.z; s_ey[PAD + 2 * i + 1] = w.w;
        }
    } else {
        // ---- phase 1 (threads 0..63): (M+1)-tap conv + GRU per stroke n ----
        const int n = tid;
        float h0 = conv_b[0], h1 = conv_b[1];
        #pragma unroll 8
        for (int h = 0; h < Mn; h++) {
            float2 v = qf[h * Nn + n];
            h0 = fmaf(v.x, conv_w[h],      fmaf(v.y, conv_w[33 + h], h0));
            h1 = fmaf(v.x, conv_w[66 + h], fmaf(v.y, conv_w[99 + h], h1));
        }
        const float2 hv = ((const float2*)ht1)[b * Nn + n];
        h0 = fmaf(hv.x, conv_w[32], fmaf(hv.y, conv_w[65],  h0));
        h1 = fmaf(hv.x, conv_w[98], fmaf(hv.y, conv_w[131], h1));

        const float x0 = zt[b * Nn + n];
        const float x1 = alpha_t[b * Nn + n];

        float r0 = sigmoidf_(fmaf(x0, W_xr[0], fmaf(x1, W_xr[2], fmaf(h0, W_hr[0], fmaf(h1, W_hr[2], b_r[0])))));
        float r1 = sigmoidf_(fmaf(x0, W_xr[1], fmaf(x1, W_xr[3], fmaf(h0, W_hr[1], fmaf(h1, W_hr[3], b_r[1])))));
        float u0 = sigmoidf_(fmaf(x0, W_xu[0], fmaf(x1, W_xu[2], fmaf(h0, W_hu[0], fmaf(h1, W_hu[2], b_u[0])))));
        float u1 = sigmoidf_(fmaf(x0, W_xu[1], fmaf(x1, W_xu[3], fmaf(h0, W_hu[1], fmaf(h1, W_hu[3], b_u[1])))));

        const float rh0 = r0 * h0, rh1 = r1 * h1;
        float nt0 = tanhf(fmaf(x0, W_xn[0], fmaf(x1, W_xn[2], fmaf(rh0, W_hn[0], fmaf(rh1, W_hn[2], b_n[0])))));
        float nt1 = tanhf(fmaf(x0, W_xn[1], fmaf(x1, W_xn[3], fmaf(rh0, W_hn[1], fmaf(rh1, W_hn[3], b_n[1])))));

        const float hn0 = u0 * hv.x + (1.0f - u0) * nt0;
        const float hn1 = u1 * hv.y + (1.0f - u1) * nt1;

        s_ht[2 * n + 0] = hn0;
        s_ht[2 * n + 1] = hn1;

        const size_t off_ht = (size_t)Bn * Nn * 2 + (size_t)Bn * Mn * Nn * 2;
        out[off_ht + ((size_t)b * Nn + n) * 2 + 0] = hn0;
        out[off_ht + ((size_t)b * Nn + n) * 2 + 1] = hn1;
    }
    __syncthreads();

    // ---- phase 2 (threads 0..63): it[n] = ht_flat . lin_w[n] + lin_b[n]; coef = it*alpha ----
    if (tid < 64) {
        const int n = tid;
        float acc = lin_b[n];
        const float* lw = lin_w + (size_t)n * 2 * Nn;
        #pragma unroll 16
        for (int j = 0; j < 2 * Nn; j++) acc = fmaf(s_ht[j], lw[j], acc);
        const float c = acc * alpha_t[b * Nn + n];
        s_coef2[n] = pack2(c, c);
    }
    __syncthreads();

    // ---- phase 3: FIR overlap-add, per-thread sliding window over 11 consecutive p ----
    // acc[i] accumulates f[p0+i] = sum_n coef[n] * emb[p0+i-n] (zero pads handle edges)
    const int p0 = tid * Cn;
    ull acc[Cn], w[Cn];
    #pragma unroll
    for (int i = 0; i < Cn; i++) {
        w[i] = pack2(s_ex[PAD + p0 + i], s_ey[PAD + p0 + i]);
        acc[i] = 0ULL;
    }
    #pragma unroll
    for (int n = 0; n < Nn; n++) {
        if (n) {
            #pragma unroll
            for (int i = Cn - 1; i > 0; i--) w[i] = w[i - 1];
            w[0] = pack2(s_ex[PAD + p0 - n], s_ey[PAD + p0 - n]);  // stride 11 words: conflict-free
        }
        const ull c2 = s_coef2[n];                                  // broadcast
        #pragma unroll
        for (int i = 0; i < Cn; i++) acc[i] = ffma2(c2, w[i], acc[i]);
    }

    // ---- output assembly ----
    // p < N: st[b,p] = q_row0[p] + f[p]
    // p >= N: qt[b, p-N] = (p < M*N ? q_flat[p] : 0) + f[p]   (q_shift[j] = q_flat[j+N] = q_flat[p])
    float2* st_out = (float2*)out + (size_t)b * Nn;
    float2* qt_out = (float2*)(out + (size_t)Bn * Nn * 2) + (size_t)b * Mn * Nn;
    #pragma unroll
    for (int i = 0; i < Cn; i++) {
        const int p = p0 + i;
        float fx, fy; unpack2(acc[i], fx, fy);
        float2 qv = make_float2(0.0f, 0.0f);
        if (p < Mn * Nn) qv = qf[p];
        float2 r = make_float2(qv.x + fx, qv.y + fy);
        if (p < Nn) st_out[p] = r;
        else        qt_out[p - Nn] = r;
    }
}

extern "C" void kernel_launch(void* const* d_in, const int* in_sizes, int n_in,
                              void* d_out, int out_size) {
    const float* qt1     = (const float*)d_in[0];
    const float* ht1     = (const float*)d_in[1];
    const float* zt      = (const float*)d_in[2];
    const float* alpha_t = (const float*)d_in[3];
    const float* conv_w  = (const float*)d_in[4];
    const float* conv_b  = (const float*)d_in[5];
    const float* W_xr    = (const float*)d_in[6];
    const float* W_hr    = (const float*)d_in[7];
    const float* b_r     = (const float*)d_in[8];
    const float* W_xu    = (const float*)d_in[9];
    const float* W_hu    = (const float*)d_in[10];
    const float* b_u     = (const float*)d_in[11];
    const float* W_xn    = (const float*)d_in[12];
    const float* W_hn    = (const float*)d_in[13];
    const float* b_n     = (const float*)d_in[14];
    const float* lin_w   = (const float*)d_in[15];
    const float* lin_b   = (const float*)d_in[16];
    const float* W_emb   = (const float*)d_in[17];

    gen_cell_kernel<<<Bn, NT>>>(qt1, ht1, zt, alpha_t, conv_w, conv_b,
                                W_xr, W_hr, b_r, W_xu, W_hu, b_u,
                                W_xn, W_hn, b_n, lin_w, lin_b, W_emb,
                                (float*)d_out);
}